// round 12
// baseline (speedup 1.0000x reference)
#include <cuda_runtime.h>
#include <cuda_bf16.h>

#define MARGIN 0.5f
#define EPS 1e-6f
#define WARPS_PER_BLOCK 8
#define THREADS (WARPS_PER_BLOCK * 32)
#define NSM 148
#define BLOCKS_PER_SM 4

// Allocation-free scratch; last finishing block resets for graph replays.
__device__ double g_sum = 0.0;
__device__ unsigned int g_count = 0u;

// Anchor/positive rows: keep resident in L1 (reused ~2x within a class).
__device__ __forceinline__ float4 ldg_keep(const float4* p)
{
    float4 v;
    asm("ld.global.nc.L1::evict_last.v4.f32 {%0,%1,%2,%3}, [%4];"
        : "=f"(v.x), "=f"(v.y), "=f"(v.z), "=f"(v.w) : "l"(p));
    return v;
}

// Negative rows: zero reuse -> don't allocate in L1 (no pollution).
__device__ __forceinline__ float4 ldg_stream(const float4* p)
{
    float4 v;
    asm("ld.global.nc.L1::no_allocate.v4.f32 {%0,%1,%2,%3}, [%4];"
        : "=f"(v.x), "=f"(v.y), "=f"(v.z), "=f"(v.w) : "l"(p));
    return v;
}

__device__ __forceinline__ float dsq(const float4 a, const float4 b)
{
    float d0 = a.x - b.x + EPS;
    float d1 = a.y - b.y + EPS;
    float d2 = a.z - b.z + EPS;
    float d3 = a.w - b.w + EPS;
    return fmaf(d0, d0, fmaf(d1, d1, fmaf(d2, d2, d3 * d3)));
}

// Half-warp per triplet, dense 256B addressing, 12 gathers in flight,
// SM-affinity block remap, L1 policy split: keep anchors/positives,
// stream negatives.
__global__ void __launch_bounds__(THREADS, 4) triplet_kernel(
    const float* __restrict__ emb,
    const int* __restrict__ a_idx,
    const int* __restrict__ p_idx,
    const int* __restrict__ n_idx,
    int T,
    float* __restrict__ out)
{
    const int lane = threadIdx.x & 31;
    const int h = lane >> 4;      // which half-warp
    const int s = lane & 15;      // sublane within half
    const int warp_in_block = threadIdx.x >> 5;

    // Virtual block id: co-resident blocks get consecutive vb.
    const int vb = (blockIdx.x % NSM) * BLOCKS_PER_SM + (blockIdx.x / NSM);
    const int gwarp = vb * WARPS_PER_BLOCK + warp_in_block;
    const int nwarps = gridDim.x * WARPS_PER_BLOCK;

    float acc = 0.0f;

    for (int t0 = gwarp * 4; t0 < T; t0 += nwarps * 4) {
        const int tA = t0 + h;          // group A triplets: t0, t0+1
        const int tB = t0 + 2 + h;      // group B triplets: t0+2, t0+3
        const bool vA = (tA < T);
        const bool vB = (tB < T);
        const int cA = vA ? tA : 0;
        const int cB = vB ? tB : 0;

        const int iaA = a_idx[cA], ipA = p_idx[cA], inA = n_idx[cA];
        const int iaB = a_idx[cB], ipB = p_idx[cB], inB = n_idx[cB];

        const float4* raA = reinterpret_cast<const float4*>(emb + (size_t)iaA * 128) + s;
        const float4* rpA = reinterpret_cast<const float4*>(emb + (size_t)ipA * 128) + s;
        const float4* rnA = reinterpret_cast<const float4*>(emb + (size_t)inA * 128) + s;
        const float4* raB = reinterpret_cast<const float4*>(emb + (size_t)iaB * 128) + s;
        const float4* rpB = reinterpret_cast<const float4*>(emb + (size_t)ipB * 128) + s;
        const float4* rnB = reinterpret_cast<const float4*>(emb + (size_t)inB * 128) + s;

        // Issue all 12 loads up front (each covers two dense 256B blocks).
        const float4 aA0 = ldg_keep(raA),     aA1 = ldg_keep(raA + 16);
        const float4 pA0 = ldg_keep(rpA),     pA1 = ldg_keep(rpA + 16);
        const float4 nA0 = ldg_stream(rnA),   nA1 = ldg_stream(rnA + 16);
        const float4 aB0 = ldg_keep(raB),     aB1 = ldg_keep(raB + 16);
        const float4 pB0 = ldg_keep(rpB),     pB1 = ldg_keep(rpB + 16);
        const float4 nB0 = ldg_stream(rnB),   nB1 = ldg_stream(rnB + 16);

        float spA = dsq(aA0, pA0) + dsq(aA1, pA1);
        float snA = dsq(aA0, nA0) + dsq(aA1, nA1);
        float spB = dsq(aB0, pB0) + dsq(aB1, pB1);
        float snB = dsq(aB0, nB0) + dsq(aB1, nB1);

        // Reduce within each 16-lane half (both halves in parallel).
        #pragma unroll
        for (int off = 8; off > 0; off >>= 1) {
            spA += __shfl_down_sync(0xFFFFFFFFu, spA, off, 16);
            snA += __shfl_down_sync(0xFFFFFFFFu, snA, off, 16);
            spB += __shfl_down_sync(0xFFFFFFFFu, spB, off, 16);
            snB += __shfl_down_sync(0xFFFFFFFFu, snB, off, 16);
        }

        if (s == 0) {
            if (vA) acc += fmaxf(sqrtf(spA) - sqrtf(snA) + MARGIN, 0.0f);
            if (vB) acc += fmaxf(sqrtf(spB) - sqrtf(snB) + MARGIN, 0.0f);
        }
    }

    // Full warp reduce of acc (nonzero in lanes 0 and 16).
    #pragma unroll
    for (int off = 16; off > 0; off >>= 1)
        acc += __shfl_down_sync(0xFFFFFFFFu, acc, off);

    __shared__ float warp_vals[WARPS_PER_BLOCK];
    if (lane == 0) warp_vals[warp_in_block] = acc;
    __syncthreads();

    if (warp_in_block == 0) {
        float v = (lane < WARPS_PER_BLOCK) ? warp_vals[lane] : 0.0f;
        #pragma unroll
        for (int off = 4; off > 0; off >>= 1)
            v += __shfl_down_sync(0xFFFFFFFFu, v, off);

        if (lane == 0) {
            atomicAdd(&g_sum, (double)v);
            __threadfence();
            unsigned int prev = atomicAdd(&g_count, 1u);
            if (prev == gridDim.x - 1) {
                double total = atomicAdd(&g_sum, 0.0);
                out[0] = (float)(total / (double)T);
                g_sum = 0.0;
                __threadfence();
                atomicExch(&g_count, 0u);
            }
        }
    }
}

extern "C" void kernel_launch(void* const* d_in, const int* in_sizes, int n_in,
                              void* d_out, int out_size) {
    const float* emb   = (const float*)d_in[0];
    // d_in[1] = labels (unused; mining is precomputed in the reference inputs)
    const int* a_idx   = (const int*)d_in[2];
    const int* p_idx   = (const int*)d_in[3];
    const int* n_idx   = (const int*)d_in[4];
    float* out         = (float*)d_out;

    const int T = in_sizes[2];

    // Exactly 4 resident blocks per SM on 148 SMs (the remap assumes it).
    int blocks = NSM * BLOCKS_PER_SM;
    int max_blocks = (T + WARPS_PER_BLOCK * 4 - 1) / (WARPS_PER_BLOCK * 4);
    if (blocks > max_blocks) blocks = max_blocks;
    if (blocks < 1) blocks = 1;

    triplet_kernel<<<blocks, THREADS>>>(emb, a_idx, p_idx, n_idx, T, out);
}